// round 4
// baseline (speedup 1.0000x reference)
#include <cuda_runtime.h>

// y = exp(i * LZ * DPHI) * x, elementwise.
// ifft2(fft2(x) * scalar) == scalar * x by linearity of the FFT.
// LZ*DPHI = 0.05 -> c = cos(0.05) + i*sin(0.05)
//
// Inputs:  d_in[0] = x_real [B*M*N] f32, d_in[1] = x_imag [B*M*N] f32
// Output:  d_out [2*B*M*N] f32, first half = real(y), second half = imag(y)
//
// Pure HBM-bound stream: 256 MB read + 256 MB write, zero reuse. Measured at
// ~6.4-6.5 TB/s across three shapes = B300 mixed R/W DRAM ceiling.
// R4: persistent grid-stride (exact-fit grid 148 SMs x 8 CTAs) to eliminate
// ~28 wave transitions and keep L1tex queues in steady state.

#define COS_C 0.9987502603949663f
#define SIN_C 0.0499791692706783f

__global__ void __launch_bounds__(256, 8)
freq_shift_kernel(const float4* __restrict__ xr,
                  const float4* __restrict__ xi,
                  float4* __restrict__ yr,
                  float4* __restrict__ yi,
                  int n4)
{
    const int stride = gridDim.x * blockDim.x;
    for (int i = blockIdx.x * blockDim.x + threadIdx.x; i < n4; i += stride) {
        float4 r = xr[i];
        float4 m = xi[i];

        float4 orr, oii;
        orr.x = fmaf(r.x, COS_C, -m.x * SIN_C);
        orr.y = fmaf(r.y, COS_C, -m.y * SIN_C);
        orr.z = fmaf(r.z, COS_C, -m.z * SIN_C);
        orr.w = fmaf(r.w, COS_C, -m.w * SIN_C);

        oii.x = fmaf(r.x, SIN_C, m.x * COS_C);
        oii.y = fmaf(r.y, SIN_C, m.y * COS_C);
        oii.z = fmaf(r.z, SIN_C, m.z * COS_C);
        oii.w = fmaf(r.w, SIN_C, m.w * COS_C);

        yr[i] = orr;
        yi[i] = oii;
    }
}

extern "C" void kernel_launch(void* const* d_in, const int* in_sizes, int n_in,
                              void* d_out, int out_size)
{
    const float* x_real = (const float*)d_in[0];
    const float* x_imag = (const float*)d_in[1];
    float* out = (float*)d_out;

    const int n = in_sizes[0];          // B*M*N = 33,554,432
    const int n4 = n / 4;

    float* out_real = out;
    float* out_imag = out + n;

    const int threads = 256;
    const int blocks = 148 * 8;         // persistent: one wave, exact-fit at occ=8

    freq_shift_kernel<<<blocks, threads>>>(
        (const float4*)x_real, (const float4*)x_imag,
        (float4*)out_real, (float4*)out_imag, n4);
}

// round 5
// speedup vs baseline: 1.1089x; 1.1089x over previous
#include <cuda_runtime.h>

// y = exp(i * LZ * DPHI) * x, elementwise.
// ifft2(fft2(x) * scalar) == scalar * x by linearity of the FFT.
// LZ*DPHI = 0.05 -> c = cos(0.05) + i*sin(0.05)
//
// Inputs:  d_in[0] = x_real [B*M*N] f32, d_in[1] = x_imag [B*M*N] f32
// Output:  d_out [2*B*M*N] f32, first half = real(y), second half = imag(y)
//
// Pure HBM-bound stream: 256 MB read + 256 MB write, zero reuse.
// Structure = R1 winner (flat launch, 1 float4/thread/stream, 24 regs).
// Isolated change: evict-first (.cs) on STORES only, so write sectors don't
// displace in-flight read fills in L2. Loads stay default-cached.

#define COS_C 0.9987502603949663f
#define SIN_C 0.0499791692706783f

__device__ __forceinline__ void st_cs(float4* p, float4 v) {
    asm volatile("st.global.cs.v4.f32 [%0], {%1,%2,%3,%4};"
                 :: "l"(p), "f"(v.x), "f"(v.y), "f"(v.z), "f"(v.w)
                 : "memory");
}

__global__ void __launch_bounds__(256, 8)
freq_shift_kernel(const float4* __restrict__ xr,
                  const float4* __restrict__ xi,
                  float4* __restrict__ yr,
                  float4* __restrict__ yi,
                  int n4)
{
    int i = blockIdx.x * blockDim.x + threadIdx.x;
    if (i >= n4) return;

    float4 r = xr[i];
    float4 m = xi[i];

    float4 orr, oii;
    orr.x = fmaf(r.x, COS_C, -m.x * SIN_C);
    orr.y = fmaf(r.y, COS_C, -m.y * SIN_C);
    orr.z = fmaf(r.z, COS_C, -m.z * SIN_C);
    orr.w = fmaf(r.w, COS_C, -m.w * SIN_C);

    oii.x = fmaf(r.x, SIN_C, m.x * COS_C);
    oii.y = fmaf(r.y, SIN_C, m.y * COS_C);
    oii.z = fmaf(r.z, SIN_C, m.z * COS_C);
    oii.w = fmaf(r.w, SIN_C, m.w * COS_C);

    st_cs(yr + i, orr);
    st_cs(yi + i, oii);
}

extern "C" void kernel_launch(void* const* d_in, const int* in_sizes, int n_in,
                              void* d_out, int out_size)
{
    const float* x_real = (const float*)d_in[0];
    const float* x_imag = (const float*)d_in[1];
    float* out = (float*)d_out;

    const int n = in_sizes[0];          // B*M*N = 33,554,432
    const int n4 = n / 4;

    float* out_real = out;
    float* out_imag = out + n;

    const int threads = 256;
    const int blocks = (n4 + threads - 1) / threads;

    freq_shift_kernel<<<blocks, threads>>>(
        (const float4*)x_real, (const float4*)x_imag,
        (float4*)out_real, (float4*)out_imag, n4);
}

// round 6
// speedup vs baseline: 1.1194x; 1.0095x over previous
#include <cuda_runtime.h>

// y = exp(i * LZ * DPHI) * x, elementwise.
// ifft2(fft2(x) * scalar) == scalar * x by linearity of the FFT.
// LZ*DPHI = 0.05 -> c = cos(0.05) + i*sin(0.05)
//
// Inputs:  d_in[0] = x_real [B*M*N] f32, d_in[1] = x_imag [B*M*N] f32
// Output:  d_out [2*B*M*N] f32, first half = real(y), second half = imag(y)
//
// Pure HBM-bound stream: 256 MB read + 256 MB write, zero reuse. Converged at
// ~6.47 TB/s = B300 mixed R/W DRAM ceiling across 5 structural variants.
// R6 (final isolated knob): 128-thread blocks -> 65536 CTAs, finer-grained
// CTA replenishment / smaller per-CTA drain quantum. Everything else = R1.

#define COS_C 0.9987502603949663f
#define SIN_C 0.0499791692706783f

__global__ void __launch_bounds__(128, 16)
freq_shift_kernel(const float4* __restrict__ xr,
                  const float4* __restrict__ xi,
                  float4* __restrict__ yr,
                  float4* __restrict__ yi,
                  int n4)
{
    int i = blockIdx.x * blockDim.x + threadIdx.x;
    if (i >= n4) return;

    float4 r = xr[i];
    float4 m = xi[i];

    float4 orr, oii;
    orr.x = fmaf(r.x, COS_C, -m.x * SIN_C);
    orr.y = fmaf(r.y, COS_C, -m.y * SIN_C);
    orr.z = fmaf(r.z, COS_C, -m.z * SIN_C);
    orr.w = fmaf(r.w, COS_C, -m.w * SIN_C);

    oii.x = fmaf(r.x, SIN_C, m.x * COS_C);
    oii.y = fmaf(r.y, SIN_C, m.y * COS_C);
    oii.z = fmaf(r.z, SIN_C, m.z * COS_C);
    oii.w = fmaf(r.w, SIN_C, m.w * COS_C);

    yr[i] = orr;
    yi[i] = oii;
}

extern "C" void kernel_launch(void* const* d_in, const int* in_sizes, int n_in,
                              void* d_out, int out_size)
{
    const float* x_real = (const float*)d_in[0];
    const float* x_imag = (const float*)d_in[1];
    float* out = (float*)d_out;

    const int n = in_sizes[0];          // B*M*N = 33,554,432
    const int n4 = n / 4;

    float* out_real = out;
    float* out_imag = out + n;

    const int threads = 128;
    const int blocks = (n4 + threads - 1) / threads;

    freq_shift_kernel<<<blocks, threads>>>(
        (const float4*)x_real, (const float4*)x_imag,
        (float4*)out_real, (float4*)out_imag, n4);
}